// round 2
// baseline (speedup 1.0000x reference)
#include <cuda_runtime.h>
#include <cstdint>
#include <cstddef>

// Problem constants
#define T_TOKENS 65536   // 64*128*8
#define DDIM     256
#define PROTOS   512
#define BM       128     // tokens per block
#define BN       128     // proto chunk
#define NCHUNK   4       // PROTOS / BN
#define KSLICE   64
#define NSLICE   4       // DDIM / KSLICE
#define THREADS  256
#define NBLOCKS  (T_TOKENS / BM)   // 512

__device__ float g_pnorm[PROTOS];
__device__ float g_partials[NBLOCKS];

// ---------------------------------------------------------------------------
// Packed fp32x2 helpers (sm_100+: fma.rn.f32x2 — FFMA2 in SASS)
// ---------------------------------------------------------------------------
__device__ __forceinline__ unsigned long long pack2(float v) {
    unsigned long long r;
    asm("mov.b64 %0, {%1, %1};" : "=l"(r) : "r"(__float_as_uint(v)));
    return r;
}
__device__ __forceinline__ void ffma2(unsigned long long& acc,
                                      unsigned long long a,
                                      unsigned long long b) {
    asm("fma.rn.f32x2 %0, %1, %2, %0;" : "+l"(acc) : "l"(a), "l"(b));
}
__device__ __forceinline__ float2 unpack2(unsigned long long v) {
    unsigned int lo, hi;
    asm("mov.b64 {%0, %1}, %2;" : "=r"(lo), "=r"(hi) : "l"(v));
    return make_float2(__uint_as_float(lo), __uint_as_float(hi));
}

// ---------------------------------------------------------------------------
// Prototype squared norms
// ---------------------------------------------------------------------------
__global__ void pnorm_kernel(const float4* __restrict__ p4) {
    int n = blockIdx.x * blockDim.x + threadIdx.x;
    if (n < PROTOS) {
        float s = 0.f;
        #pragma unroll 8
        for (int kq = 0; kq < DDIM / 4; ++kq) {
            float4 v = p4[(size_t)n * (DDIM / 4) + kq];
            s += v.x * v.x + v.y * v.y + v.z * v.z + v.w * v.w;
        }
        g_pnorm[n] = s;
    }
}

// ---------------------------------------------------------------------------
// Main fused kernel: distance GEMM (FFMA2) + argmin + gather + residual + loss
// ---------------------------------------------------------------------------
__global__ __launch_bounds__(THREADS, 1)
void vq_main_kernel(const float4* __restrict__ x4,
                    const float4* __restrict__ p4,
                    float4* __restrict__ out_proto,
                    float4* __restrict__ out_res) {
    extern __shared__ float sm[];
    float* sxT  = sm;                         // [DDIM][BM]  x transposed
    float* sp   = sm + DDIM * BM;             // [KSLICE][BN] proto slice
    int*   sidx = (int*)(sp + KSLICE * BN);   // [BM]
    float* sred = (float*)(sidx + BM);        // [THREADS]

    const int tid = threadIdx.x;
    const int tx  = tid & 15;    // proto dim (16)
    const int ty  = tid >> 4;    // token dim (16)
    const int t0  = blockIdx.x * BM;

    // Load x tile transposed: sxT[k][m]. Lanes have consecutive m -> STS conflict-free.
    for (int i = tid; i < BM * (DDIM / 4); i += THREADS) {
        int t  = i & (BM - 1);
        int kq = i >> 7;
        float4 v = x4[(size_t)(t0 + t) * (DDIM / 4) + kq];
        sxT[(4 * kq + 0) * BM + t] = v.x;
        sxT[(4 * kq + 1) * BM + t] = v.y;
        sxT[(4 * kq + 2) * BM + t] = v.z;
        sxT[(4 * kq + 3) * BM + t] = v.w;
    }

    float best[8];
    int   bidx[8];
    #pragma unroll
    for (int i = 0; i < 8; i++) { best[i] = 3.4e38f; bidx[i] = 0; }

    for (int c = 0; c < NCHUNK; ++c) {
        // 8 tokens x 8 protos per thread; protos paired -> 8x4 packed accumulators.
        unsigned long long acc[8][4];
        #pragma unroll
        for (int i = 0; i < 8; i++)
            #pragma unroll
            for (int j = 0; j < 4; j++) acc[i][j] = 0ull;

        for (int s = 0; s < NSLICE; ++s) {
            __syncthreads();   // prior compute done before sp overwrite (also fences x load, 1st iter)
            // Load proto K-slice: sp[kl][n]
            for (int i = tid; i < BN * (KSLICE / 4); i += THREADS) {
                int n  = i & (BN - 1);
                int kq = i >> 7;   // 0..15
                float4 v = p4[(size_t)(c * BN + n) * (DDIM / 4) + s * (KSLICE / 4) + kq];
                sp[(4 * kq + 0) * BN + n] = v.x;
                sp[(4 * kq + 1) * BN + n] = v.y;
                sp[(4 * kq + 2) * BN + n] = v.z;
                sp[(4 * kq + 3) * BN + n] = v.w;
            }
            __syncthreads();

            const float* xrow = sxT + (s * KSLICE) * BM + ty * 8;
            const float* prow = sp + tx * 8;
            #pragma unroll 4
            for (int k = 0; k < KSLICE; ++k) {
                float4 a0 = *(const float4*)(xrow + k * BM);
                float4 a1 = *(const float4*)(xrow + k * BM + 4);
                unsigned long long A[8];
                A[0] = pack2(a0.x); A[1] = pack2(a0.y);
                A[2] = pack2(a0.z); A[3] = pack2(a0.w);
                A[4] = pack2(a1.x); A[5] = pack2(a1.y);
                A[6] = pack2(a1.z); A[7] = pack2(a1.w);
                const ulonglong2* bp = (const ulonglong2*)(prow + k * BN);
                ulonglong2 q0 = bp[0];   // protos n0+0..3 (two packed pairs)
                ulonglong2 q1 = bp[1];   // protos n0+4..7
                unsigned long long B[4] = {q0.x, q0.y, q1.x, q1.y};
                #pragma unroll
                for (int mi = 0; mi < 8; ++mi)
                    #pragma unroll
                    for (int nj = 0; nj < 4; ++nj)
                        ffma2(acc[mi][nj], A[mi], B[nj]);
            }
        }

        // Merge this chunk into running argmin. dist = ||p||^2 - 2*dot (token norm constant).
        #pragma unroll
        for (int njp = 0; njp < 4; ++njp) {
            int   ng  = c * BN + tx * 8 + 2 * njp;
            float pn0 = g_pnorm[ng];
            float pn1 = g_pnorm[ng + 1];
            #pragma unroll
            for (int mi = 0; mi < 8; ++mi) {
                float2 d = unpack2(acc[mi][njp]);
                float d0 = fmaf(-2.f, d.x, pn0);
                float d1 = fmaf(-2.f, d.y, pn1);
                if (d0 < best[mi]) { best[mi] = d0; bidx[mi] = ng; }
                if (d1 < best[mi]) { best[mi] = d1; bidx[mi] = ng + 1; }
            }
        }
    }

    // Reduce argmin across the 16 proto-dim lanes (lanes 0-15 / 16-31 within warp).
    #pragma unroll
    for (int off = 8; off >= 1; off >>= 1) {
        #pragma unroll
        for (int mi = 0; mi < 8; ++mi) {
            float od = __shfl_xor_sync(0xffffffffu, best[mi], off);
            int   oi = __shfl_xor_sync(0xffffffffu, bidx[mi], off);
            if (od < best[mi] || (od == best[mi] && oi < bidx[mi])) {
                best[mi] = od; bidx[mi] = oi;
            }
        }
    }
    if (tx == 0) {
        #pragma unroll
        for (int mi = 0; mi < 8; ++mi) sidx[ty * 8 + mi] = bidx[mi];
    }
    __syncthreads();

    // Epilogue: gather prototype, write proto + residual (coalesced), loss partial.
    float lsum = 0.f;
    for (int i = tid; i < BM * (DDIM / 4); i += THREADS) {
        int t  = i >> 6;        // lanes share t, walk kq -> coalesced
        int kq = i & 63;
        int id = sidx[t];
        float4 pv = p4[(size_t)id * (DDIM / 4) + kq];
        float4 xv = x4[(size_t)(t0 + t) * (DDIM / 4) + kq];
        float4 rv = make_float4(xv.x - pv.x, xv.y - pv.y, xv.z - pv.z, xv.w - pv.w);
        size_t o = (size_t)(t0 + t) * (DDIM / 4) + kq;
        out_proto[o] = pv;
        out_res[o]   = rv;
        lsum += rv.x * rv.x + rv.y * rv.y + rv.z * rv.z + rv.w * rv.w;
    }

    // Deterministic block reduction of loss partial.
    sred[tid] = lsum;
    __syncthreads();
    #pragma unroll
    for (int s2 = THREADS / 2; s2 >= 1; s2 >>= 1) {
        if (tid < s2) sred[tid] += sred[tid + s2];
        __syncthreads();
    }
    if (tid == 0) g_partials[blockIdx.x] = sred[0];
}

// ---------------------------------------------------------------------------
// Deterministic final loss reduction
// ---------------------------------------------------------------------------
__global__ void finalize_kernel(float* __restrict__ loss_out) {
    __shared__ float s[NBLOCKS];
    int tid = threadIdx.x;
    s[tid] = g_partials[tid];
    __syncthreads();
    #pragma unroll
    for (int st = NBLOCKS / 2; st >= 1; st >>= 1) {
        if (tid < st) s[tid] += s[tid + st];
        __syncthreads();
    }
    if (tid == 0) {
        // loss = q_latent + 0.25 * e_latent = 1.25 * mean((proto - x)^2)
        *loss_out = 1.25f * s[0] / 16777216.0f;
    }
}

// ---------------------------------------------------------------------------
extern "C" void kernel_launch(void* const* d_in, const int* in_sizes, int n_in,
                              void* d_out, int out_size) {
    const float4* x4 = (const float4*)d_in[0];
    const float4* p4 = (const float4*)d_in[1];
    float* out = (float*)d_out;

    float4* out_proto = (float4*)out;                          // [65536, 256]
    float4* out_res   = (float4*)(out + 16777216);             // [65536, 256]
    float*  loss_out  = out + 33554432;                        // scalar

    const int smem_bytes = (DDIM * BM + KSLICE * BN) * 4 + BM * 4 + THREADS * 4;
    cudaFuncSetAttribute(vq_main_kernel,
                         cudaFuncAttributeMaxDynamicSharedMemorySize, smem_bytes);

    pnorm_kernel<<<2, 256>>>(p4);
    vq_main_kernel<<<NBLOCKS, THREADS, smem_bytes>>>(x4, p4, out_proto, out_res);
    finalize_kernel<<<1, NBLOCKS>>>(loss_out);
}

// round 4
// speedup vs baseline: 1.3416x; 1.3416x over previous
#include <cuda_runtime.h>
#include <cstdint>
#include <cstddef>

// ===========================================================================
// Problem constants
// ===========================================================================
#define T_TOKENS 65536
#define DDIM     256
#define PROTOS   512
#define BM       128          // tokens per CTA
#define BN       128          // protos per chunk
#define NCHUNK   4
#define KS       32           // K-slice for streamed B
#define NSLICES  32           // NCHUNK * (DDIM/KS)
#define THREADS  256
#define NBLOCKS  (T_TOKENS / BM)   // 512

// Shared memory layout (bytes)
#define SLOT_OFF 0                         // 128 x u64 argmin slots
#define A_OFF    1024                      // 128 x 260 fp32  (133120 B)
#define B_OFF    (A_OFF + 128*260*4)       // 2 bufs x 2 splits x 128 x 36 fp32
#define B_BUFB   (2*128*36*4)              // 36864 per buffer
#define B_SPLITB (128*36*4)                // 18432 per split
#define PN_OFF   (B_OFF + 2*B_BUFB)        // 512 fp32
#define SRED_OFF (PN_OFF + 512*4)          // 256 fp32
#define SMEM_TOTAL (SRED_OFF + 256*4)      // 210944

__device__ float g_Bh[PROTOS * DDIM];
__device__ float g_Bl[PROTOS * DDIM];
__device__ float g_pnorm[PROTOS];
__device__ float g_partials[NBLOCKS];

// ===========================================================================
// Helpers
// ===========================================================================
__device__ __forceinline__ uint32_t smem_u32(const void* p) {
    uint32_t a;
    asm("{ .reg .u64 t; cvta.to.shared.u64 t, %1; cvt.u32.u64 %0, t; }" : "=r"(a) : "l"(p));
    return a;
}
__device__ __forceinline__ void cp_async16(uint32_t dst, const void* src) {
    asm volatile("cp.async.cg.shared.global [%0], [%1], 16;" :: "r"(dst), "l"(src) : "memory");
}
__device__ __forceinline__ void cp_commit() {
    asm volatile("cp.async.commit_group;" ::: "memory");
}
__device__ __forceinline__ void cp_wait1() {
    asm volatile("cp.async.wait_group 1;" ::: "memory");
}
__device__ __forceinline__ void cp_wait0() {
    asm volatile("cp.async.wait_group 0;" ::: "memory");
}
// D += A(tf32) * B(tf32), m16n8k8, A row-major, B col-major
__device__ __forceinline__ void mma_tf32(float* d, const uint32_t* a, const uint32_t* b) {
    asm volatile(
        "mma.sync.aligned.m16n8k8.row.col.f32.tf32.tf32.f32 "
        "{%0,%1,%2,%3}, {%4,%5,%6,%7}, {%8,%9}, {%0,%1,%2,%3};"
        : "+f"(d[0]), "+f"(d[1]), "+f"(d[2]), "+f"(d[3])
        : "r"(a[0]), "r"(a[1]), "r"(a[2]), "r"(a[3]), "r"(b[0]), "r"(b[1]));
}
__device__ __forceinline__ uint32_t tf32_trunc(float v) {
    return __float_as_uint(v) & 0xFFFFE000u;
}

// ===========================================================================
// Prep: split prototypes into tf32 hi/lo + compute exact fp32 norms
// ===========================================================================
__global__ void prep_kernel(const float4* __restrict__ p4) {
    int r = blockIdx.x * blockDim.x + threadIdx.x;
    if (r >= PROTOS) return;
    float pn = 0.f;
    for (int kq = 0; kq < DDIM / 4; ++kq) {
        float4 v = p4[(size_t)r * (DDIM / 4) + kq];
        pn += v.x * v.x + v.y * v.y + v.z * v.z + v.w * v.w;
        float vv[4] = {v.x, v.y, v.z, v.w};
        #pragma unroll
        for (int j = 0; j < 4; ++j) {
            uint32_t hb = tf32_trunc(vv[j]);
            float lo = vv[j] - __uint_as_float(hb);
            g_Bh[r * DDIM + kq * 4 + j] = __uint_as_float(hb);
            g_Bl[r * DDIM + kq * 4 + j] = __uint_as_float(tf32_trunc(lo));
        }
    }
    g_pnorm[r] = pn;
}

// ===========================================================================
// Main kernel
// ===========================================================================
__global__ __launch_bounds__(THREADS, 1)
void vq_main_kernel(const float4* __restrict__ x4,
                    const float4* __restrict__ p4,
                    float4* __restrict__ out_proto,
                    float4* __restrict__ out_res) {
    extern __shared__ unsigned char smem[];
    const uint32_t sb = smem_u32(smem);
    unsigned long long* slots = (unsigned long long*)(smem + SLOT_OFF);
    float* Af   = (float*)(smem + A_OFF);
    float* spn  = (float*)(smem + PN_OFF);
    float* sred = (float*)(smem + SRED_OFF);

    const int tid  = threadIdx.x;
    const int lane = tid & 31;
    const int wid  = tid >> 5;
    const int q    = lane & 3;     // thread-in-group
    const int gq   = lane >> 2;    // group id (0..7)
    const int warpM = wid & 3;     // 4 warps along M (32 rows each)
    const int warpN = wid >> 2;    // 2 warps along N (64 cols each)
    const int t0 = blockIdx.x * BM;

    // --- init: slots, A tile (fp32), pnorm cache ---
    if (tid < BM) slots[tid] = 0xFFFFFFFFFFFFFFFFull;
    for (int i = tid; i < BM * (DDIM / 4); i += THREADS) {
        int m = i >> 6, kq = i & 63;
        float4 v = x4[(size_t)(t0 + m) * (DDIM / 4) + kq];
        *(float4*)(Af + m * 260 + kq * 4) = v;
    }
    for (int i = tid; i < PROTOS; i += THREADS) spn[i] = g_pnorm[i];

    float acc[2][8][4];
    #pragma unroll
    for (int mf = 0; mf < 2; ++mf)
        #pragma unroll
        for (int nf = 0; nf < 8; ++nf)
            #pragma unroll
            for (int d = 0; d < 4; ++d) acc[mf][nf][d] = 0.f;

    // --- prefetch slice 0 ---
    {
        #pragma unroll
        for (int it = 0; it < 8; ++it) {
            int flat = it * THREADS + tid;
            int sp = flat >> 10, rest = flat & 1023;
            int n = rest >> 3, kq = rest & 7;
            uint32_t dst = sb + B_OFF + sp * B_SPLITB + (n * 36 + kq * 4) * 4;
            const float* src = (sp ? g_Bl : g_Bh) + (size_t)n * DDIM + kq * 4;
            cp_async16(dst, src);
        }
        cp_commit();
    }

    #pragma unroll 1
    for (int g = 0; g < NSLICES; ++g) {
        // prefetch slice g+1 into buffer (g+1)&1
        if (g < NSLICES - 1) {
            int gn = g + 1;
            int chn = gn >> 3, sl = gn & 7, buf = gn & 1;
            #pragma unroll
            for (int it = 0; it < 8; ++it) {
                int flat = it * THREADS + tid;
                int sp = flat >> 10, rest = flat & 1023;
                int n = rest >> 3, kq = rest & 7;
                uint32_t dst = sb + B_OFF + buf * B_BUFB + sp * B_SPLITB + (n * 36 + kq * 4) * 4;
                const float* src = (sp ? g_Bl : g_Bh) + (size_t)(chn * BN + n) * DDIM + sl * KS + kq * 4;
                cp_async16(dst, src);
            }
            cp_commit();
            cp_wait1();
        } else {
            cp_wait0();
        }
        __syncthreads();

        // --- compute slice g ---
        {
            const int buf = g & 1;
            const int kA0 = (g & 7) * KS;      // global K offset within A
            const float* Bhf = (const float*)(smem + B_OFF + buf * B_BUFB);
            const float* Blf = (const float*)(smem + B_OFF + buf * B_BUFB + B_SPLITB);
            const int arow0 = warpM * 32 + gq;
            const int brow0 = warpN * 64 + gq;

            #pragma unroll
            for (int kk = 0; kk < KS / 8; ++kk) {
                const int kA = kA0 + kk * 8;
                const int kB = kk * 8;

                // A fragments: hi (truncated) + lo
                uint32_t ah[2][4], al[2][4];
                #pragma unroll
                for (int mf = 0; mf < 2; ++mf) {
                    #pragma unroll
                    for (int f = 0; f < 4; ++f) {
                        int row = arow0 + mf * 16 + (f & 1) * 8;
                        int col = kA + q + (f >> 1) * 4;
                        float xv = Af[row * 260 + col];
                        uint32_t hb = tf32_trunc(xv);
                        ah[mf][f] = hb;
                        al[mf][f] = __float_as_uint(xv - __uint_as_float(hb));
                    }
                }
                // Bh fragments
                uint32_t bh[8][2];
                #pragma unroll
                for (int nf = 0; nf < 8; ++nf)
                    #pragma unroll
                    for (int f = 0; f < 2; ++f)
                        bh[nf][f] = __float_as_uint(Bhf[(brow0 + nf * 8) * 36 + kB + q + f * 4]);
                // term hh
                #pragma unroll
                for (int mf = 0; mf < 2; ++mf)
                    #pragma unroll
                    for (int nf = 0; nf < 8; ++nf)
                        mma_tf32(acc[mf][nf], ah[mf], bh[nf]);
                // term lh
                #pragma unroll
                for (int mf = 0; mf < 2; ++mf)
                    #pragma unroll
                    for (int nf = 0; nf < 8; ++nf)
                        mma_tf32(acc[mf][nf], al[mf], bh[nf]);
                // Bl fragments + term hl
                uint32_t bl[8][2];
                #pragma unroll
                for (int nf = 0; nf < 8; ++nf)
                    #pragma unroll
                    for (int f = 0; f < 2; ++f)
                        bl[nf][f] = __float_as_uint(Blf[(brow0 + nf * 8) * 36 + kB + q + f * 4]);
                #pragma unroll
                for (int mf = 0; mf < 2; ++mf)
                    #pragma unroll
                    for (int nf = 0; nf < 8; ++nf)
                        mma_tf32(acc[mf][nf], ah[mf], bl[nf]);
            }
        }

        // --- end of chunk: fold accumulators into argmin slots ---
        if ((g & 7) == 7) {
            const int chunk = g >> 3;
            #pragma unroll
            for (int mf = 0; mf < 2; ++mf) {
                #pragma unroll
                for (int h = 0; h < 2; ++h) {
                    int row = warpM * 32 + mf * 16 + h * 8 + gq;
                    float bestd = 3.4e38f;
                    int bi = 0;
                    #pragma unroll
                    for (int nf = 0; nf < 8; ++nf) {
                        #pragma unroll
                        for (int d = 0; d < 2; ++d) {
                            int n = chunk * BN + warpN * 64 + nf * 8 + 2 * q + d;
                            float dist = fmaf(-2.f, acc[mf][nf][h * 2 + d], spn[n]);
                            if (dist < bestd) { bestd = dist; bi = n; }   // n ascending -> lowest idx kept
                        }
                    }
                    uint32_t mb = __float_as_uint(bestd);
                    mb ^= (mb & 0x80000000u) ? 0xFFFFFFFFu : 0x80000000u;  // orderable
                    unsigned long long key = ((unsigned long long)mb << 32) | (unsigned)bi;
                    atomicMin(&slots[row], key);
                }
            }
            #pragma unroll
            for (int mf = 0; mf < 2; ++mf)
                #pragma unroll
                for (int nf = 0; nf < 8; ++nf)
                    #pragma unroll
                    for (int d = 0; d < 4; ++d) acc[mf][nf][d] = 0.f;
        }
        __syncthreads();
    }

    // --- epilogue: gather exact fp32 prototype, proto + residual + loss ---
    float lsum = 0.f;
    for (int i = tid; i < BM * (DDIM / 4); i += THREADS) {
        int t  = i >> 6;
        int kq = i & 63;
        int id = (int)(slots[t] & 0xFFFFFFFFull);
        float4 pv = p4[(size_t)id * (DDIM / 4) + kq];
        float4 xv = x4[(size_t)(t0 + t) * (DDIM / 4) + kq];
        float4 rv = make_float4(xv.x - pv.x, xv.y - pv.y, xv.z - pv.z, xv.w - pv.w);
        size_t o = (size_t)(t0 + t) * (DDIM / 4) + kq;
        out_proto[o] = pv;
        out_res[o]   = rv;
        lsum += rv.x * rv.x + rv.y * rv.y + rv.z * rv.z + rv.w * rv.w;
    }
    sred[tid] = lsum;
    __syncthreads();
    #pragma unroll
    for (int s2 = THREADS / 2; s2 >= 1; s2 >>= 1) {
        if (tid < s2) sred[tid] += sred[tid + s2];
        __syncthreads();
    }
    if (tid == 0) g_partials[blockIdx.x] = sred[0];
}

// ===========================================================================
// Deterministic final loss reduction
// ===========================================================================
__global__ void finalize_kernel(float* __restrict__ loss_out) {
    __shared__ float s[NBLOCKS];
    int tid = threadIdx.x;
    s[tid] = g_partials[tid];
    __syncthreads();
    #pragma unroll
    for (int st = NBLOCKS / 2; st >= 1; st >>= 1) {
        if (tid < st) s[tid] += s[tid + st];
        __syncthreads();
    }
    if (tid == 0) {
        // loss = q_latent + 0.25 * e_latent = 1.25 * mean((proto - x)^2)
        *loss_out = 1.25f * s[0] / 16777216.0f;
    }
}

// ===========================================================================
extern "C" void kernel_launch(void* const* d_in, const int* in_sizes, int n_in,
                              void* d_out, int out_size) {
    const float4* x4 = (const float4*)d_in[0];
    const float4* p4 = (const float4*)d_in[1];
    float* out = (float*)d_out;

    float4* out_proto = (float4*)out;               // [65536, 256]
    float4* out_res   = (float4*)(out + 16777216);  // [65536, 256]
    float*  loss_out  = out + 33554432;             // scalar

    cudaFuncSetAttribute(vq_main_kernel,
                         cudaFuncAttributeMaxDynamicSharedMemorySize, SMEM_TOTAL);

    prep_kernel<<<4, 128>>>(p4);
    vq_main_kernel<<<NBLOCKS, THREADS, SMEM_TOTAL>>>(x4, p4, out_proto, out_res);
    finalize_kernel<<<1, NBLOCKS>>>(loss_out);
}

// round 5
// speedup vs baseline: 2.2691x; 1.6914x over previous
#include <cuda_runtime.h>
#include <cuda_fp16.h>
#include <cstdint>
#include <cstddef>

// ===========================================================================
// Problem constants
// ===========================================================================
#define T_TOKENS 65536
#define DDIM     256
#define PROTOS   512
#define BM       128          // tokens per CTA
#define BN       128          // protos per chunk
#define NCHUNK   4
#define KS       32           // K-slice for streamed B
#define NSLICES  32           // NCHUNK * (DDIM/KS)
#define THREADS  256
#define NBLOCKS  (T_TOKENS / BM)   // 512

// Shared memory layout (bytes)
#define SLOT_OFF 0                          // 128 x u64 argmin slots
#define PN_OFF   1024                       // 512 fp32
#define SRED_OFF 3072                       // 256 fp32
#define AH_OFF   4096
#define A_STRH   264                        // halves per A row (pad: conflict-free)
#define A_BYTES  (128 * A_STRH * 2)         // 67584
#define AL_OFF   (AH_OFF + A_BYTES)         // 71680
#define B_OFF    (AL_OFF + A_BYTES)         // 139264 (16B aligned)
#define B_STRH   40                         // halves per B row (pad: conflict-free)
#define B_SPLITB (128 * B_STRH * 2)         // 10240
#define B_BUFB   (2 * B_SPLITB)             // 20480
#define SMEM_TOTAL (B_OFF + 2 * B_BUFB)     // 180224

__device__ __half g_Bh16[PROTOS * DDIM];
__device__ __half g_Bl16[PROTOS * DDIM];
__device__ float  g_pnorm[PROTOS];
__device__ float  g_partials[NBLOCKS];

// ===========================================================================
// Helpers
// ===========================================================================
__device__ __forceinline__ uint32_t smem_u32(const void* p) {
    uint32_t a;
    asm("{ .reg .u64 t; cvta.to.shared.u64 t, %1; cvt.u32.u64 %0, t; }" : "=r"(a) : "l"(p));
    return a;
}
__device__ __forceinline__ void cp_async16(uint32_t dst, const void* src) {
    asm volatile("cp.async.cg.shared.global [%0], [%1], 16;" :: "r"(dst), "l"(src) : "memory");
}
__device__ __forceinline__ void cp_commit() {
    asm volatile("cp.async.commit_group;" ::: "memory");
}
__device__ __forceinline__ void cp_wait1() {
    asm volatile("cp.async.wait_group 1;" ::: "memory");
}
__device__ __forceinline__ void cp_wait0() {
    asm volatile("cp.async.wait_group 0;" ::: "memory");
}
// D += A(f16) * B(f16), m16n8k16, A row-major, B col-major, f32 accumulate
__device__ __forceinline__ void mma_f16(float* d, const uint32_t* a, const uint32_t* b) {
    asm volatile(
        "mma.sync.aligned.m16n8k16.row.col.f32.f16.f16.f32 "
        "{%0,%1,%2,%3}, {%4,%5,%6,%7}, {%8,%9}, {%0,%1,%2,%3};"
        : "+f"(d[0]), "+f"(d[1]), "+f"(d[2]), "+f"(d[3])
        : "r"(a[0]), "r"(a[1]), "r"(a[2]), "r"(a[3]), "r"(b[0]), "r"(b[1]));
}
// Split pair (a = even k -> low half, b = odd k -> high half) into h/l fp16 words
__device__ __forceinline__ void split_h2(float a, float b, uint32_t& hw, uint32_t& lw) {
    __half ha = __float2half_rn(a), hb = __float2half_rn(b);
    float la = a - __half2float(ha);
    float lb = b - __half2float(hb);
    __half hla = __float2half_rn(la), hlb = __float2half_rn(lb);
    hw = (uint32_t)__half_as_ushort(ha) | ((uint32_t)__half_as_ushort(hb) << 16);
    lw = (uint32_t)__half_as_ushort(hla) | ((uint32_t)__half_as_ushort(hlb) << 16);
}

// ===========================================================================
// Prep: warp-per-prototype fp16 split + shfl-reduced norms (deterministic)
// ===========================================================================
__global__ void prep_kernel(const float4* __restrict__ p4) {
    int gtid = blockIdx.x * blockDim.x + threadIdx.x;
    int r    = gtid >> 5;
    int lane = gtid & 31;
    if (r >= PROTOS) return;
    const float4* src = p4 + (size_t)r * (DDIM / 4) + lane * 2;
    float4 v0 = src[0];
    float4 v1 = src[1];
    float f[8] = {v0.x, v0.y, v0.z, v0.w, v1.x, v1.y, v1.z, v1.w};
    uint32_t hw[4], lw[4];
    float nrm = 0.f;
    #pragma unroll
    for (int j = 0; j < 4; ++j) {
        split_h2(f[2 * j], f[2 * j + 1], hw[j], lw[j]);
        nrm += f[2 * j] * f[2 * j] + f[2 * j + 1] * f[2 * j + 1];
    }
    *(uint4*)(g_Bh16 + (size_t)r * DDIM + lane * 8) = make_uint4(hw[0], hw[1], hw[2], hw[3]);
    *(uint4*)(g_Bl16 + (size_t)r * DDIM + lane * 8) = make_uint4(lw[0], lw[1], lw[2], lw[3]);
    #pragma unroll
    for (int off = 16; off >= 1; off >>= 1)
        nrm += __shfl_xor_sync(0xffffffffu, nrm, off);
    if (lane == 0) g_pnorm[r] = nrm;
}

// ===========================================================================
// Main kernel: fp16x2-split (3-term) tensor-core distance GEMM + fused VQ
// ===========================================================================
__global__ __launch_bounds__(THREADS, 1)
void vq_main_kernel(const float4* __restrict__ x4,
                    const float4* __restrict__ p4,
                    float4* __restrict__ out_proto,
                    float4* __restrict__ out_res) {
    extern __shared__ unsigned char smem[];
    const uint32_t sb = smem_u32(smem);
    unsigned long long* slots = (unsigned long long*)(smem + SLOT_OFF);
    float*  spn  = (float*)(smem + PN_OFF);
    float*  sred = (float*)(smem + SRED_OFF);
    __half* AhP  = (__half*)(smem + AH_OFF);
    __half* AlP  = (__half*)(smem + AL_OFF);

    const int tid  = threadIdx.x;
    const int lane = tid & 31;
    const int wid  = tid >> 5;
    const int q    = lane & 3;     // thread-in-group
    const int gq   = lane >> 2;    // group id (0..7)
    const int warpM = wid & 3;     // 4 warps along M (32 rows each)
    const int warpN = wid >> 2;    // 2 warps along N (64 cols each)
    const int t0 = blockIdx.x * BM;

    // --- init: slots, pnorm cache, A tile split to fp16 h/l ---
    if (tid < BM) slots[tid] = 0xFFFFFFFFFFFFFFFFull;
    for (int i = tid; i < PROTOS; i += THREADS) spn[i] = g_pnorm[i];
    for (int i = tid; i < BM * (DDIM / 4); i += THREADS) {
        int m = i >> 6, kq = i & 63;
        float4 v = x4[(size_t)(t0 + m) * (DDIM / 4) + kq];
        uint32_t h0, l0, h1, l1;
        split_h2(v.x, v.y, h0, l0);
        split_h2(v.z, v.w, h1, l1);
        *(uint2*)(AhP + m * A_STRH + kq * 4) = make_uint2(h0, h1);
        *(uint2*)(AlP + m * A_STRH + kq * 4) = make_uint2(l0, l1);
    }

    float acc[2][8][4];
    #pragma unroll
    for (int mf = 0; mf < 2; ++mf)
        #pragma unroll
        for (int nf = 0; nf < 8; ++nf)
            #pragma unroll
            for (int d = 0; d < 4; ++d) acc[mf][nf][d] = 0.f;

    // --- prefetch slice 0 ---
    {
        #pragma unroll
        for (int it = 0; it < 4; ++it) {
            int flat = it * THREADS + tid;
            int sp = flat >> 9, rest = flat & 511;
            int n = rest >> 2, gi = rest & 3;
            uint32_t dst = sb + B_OFF + sp * B_SPLITB + n * (B_STRH * 2) + gi * 16;
            const __half* src = (sp ? g_Bl16 : g_Bh16) + (size_t)n * DDIM + gi * 8;
            cp_async16(dst, src);
        }
        cp_commit();
    }

    #pragma unroll 1
    for (int g = 0; g < NSLICES; ++g) {
        // prefetch slice g+1 into buffer (g+1)&1
        if (g < NSLICES - 1) {
            int gn = g + 1;
            int chn = gn >> 3, sl = gn & 7, buf = gn & 1;
            #pragma unroll
            for (int it = 0; it < 4; ++it) {
                int flat = it * THREADS + tid;
                int sp = flat >> 9, rest = flat & 511;
                int n = rest >> 2, gi = rest & 3;
                uint32_t dst = sb + B_OFF + buf * B_BUFB + sp * B_SPLITB + n * (B_STRH * 2) + gi * 16;
                const __half* src = (sp ? g_Bl16 : g_Bh16)
                                    + (size_t)(chn * BN + n) * DDIM + sl * KS + gi * 8;
                cp_async16(dst, src);
            }
            cp_commit();
            cp_wait1();
        } else {
            cp_wait0();
        }
        __syncthreads();

        // --- compute slice g (2 x k16) ---
        {
            const int buf = g & 1;
            const __half* Bh_s = (const __half*)(smem + B_OFF + buf * B_BUFB);
            const __half* Bl_s = Bh_s + 128 * B_STRH;
            const int kA0 = (g & 7) * KS;
            const int arow0 = warpM * 32 + gq;
            const int bcol0 = warpN * 64 + gq;

            #pragma unroll
            for (int kk = 0; kk < 2; ++kk) {
                const int c0 = kA0 + kk * 16 + 2 * q;
                const int cb = kk * 16 + 2 * q;

                uint32_t ah[2][4], al[2][4];
                #pragma unroll
                for (int mf = 0; mf < 2; ++mf) {
                    int r0 = (arow0 + mf * 16) * A_STRH;
                    int r1 = r0 + 8 * A_STRH;
                    ah[mf][0] = *(const uint32_t*)(AhP + r0 + c0);
                    ah[mf][1] = *(const uint32_t*)(AhP + r1 + c0);
                    ah[mf][2] = *(const uint32_t*)(AhP + r0 + c0 + 8);
                    ah[mf][3] = *(const uint32_t*)(AhP + r1 + c0 + 8);
                    al[mf][0] = *(const uint32_t*)(AlP + r0 + c0);
                    al[mf][1] = *(const uint32_t*)(AlP + r1 + c0);
                    al[mf][2] = *(const uint32_t*)(AlP + r0 + c0 + 8);
                    al[mf][3] = *(const uint32_t*)(AlP + r1 + c0 + 8);
                }
                uint32_t bh[8][2], bl[8][2];
                #pragma unroll
                for (int nf = 0; nf < 8; ++nf) {
                    int nr = (bcol0 + nf * 8) * B_STRH;
                    bh[nf][0] = *(const uint32_t*)(Bh_s + nr + cb);
                    bh[nf][1] = *(const uint32_t*)(Bh_s + nr + cb + 8);
                    bl[nf][0] = *(const uint32_t*)(Bl_s + nr + cb);
                    bl[nf][1] = *(const uint32_t*)(Bl_s + nr + cb + 8);
                }
                // term hh
                #pragma unroll
                for (int mf = 0; mf < 2; ++mf)
                    #pragma unroll
                    for (int nf = 0; nf < 8; ++nf)
                        mma_f16(acc[mf][nf], ah[mf], bh[nf]);
                // term lh
                #pragma unroll
                for (int mf = 0; mf < 2; ++mf)
                    #pragma unroll
                    for (int nf = 0; nf < 8; ++nf)
                        mma_f16(acc[mf][nf], al[mf], bh[nf]);
                // term hl
                #pragma unroll
                for (int mf = 0; mf < 2; ++mf)
                    #pragma unroll
                    for (int nf = 0; nf < 8; ++nf)
                        mma_f16(acc[mf][nf], ah[mf], bl[nf]);
            }
        }

        // --- end of chunk: fold accumulators into argmin slots ---
        if ((g & 7) == 7) {
            const int chunk = g >> 3;
            #pragma unroll
            for (int mf = 0; mf < 2; ++mf) {
                #pragma unroll
                for (int h = 0; h < 2; ++h) {
                    int row = warpM * 32 + mf * 16 + h * 8 + gq;
                    float bestd = 3.4e38f;
                    int bi = 0;
                    #pragma unroll
                    for (int nf = 0; nf < 8; ++nf) {
                        #pragma unroll
                        for (int d = 0; d < 2; ++d) {
                            int n = chunk * BN + warpN * 64 + nf * 8 + 2 * q + d;
                            float dist = fmaf(-2.f, acc[mf][nf][h * 2 + d], spn[n]);
                            if (dist < bestd) { bestd = dist; bi = n; }
                        }
                    }
                    uint32_t mb = __float_as_uint(bestd);
                    mb ^= (mb & 0x80000000u) ? 0xFFFFFFFFu : 0x80000000u;  // orderable
                    unsigned long long key = ((unsigned long long)mb << 32) | (unsigned)bi;
                    atomicMin(&slots[row], key);
                }
            }
            #pragma unroll
            for (int mf = 0; mf < 2; ++mf)
                #pragma unroll
                for (int nf = 0; nf < 8; ++nf)
                    #pragma unroll
                    for (int d = 0; d < 4; ++d) acc[mf][nf][d] = 0.f;
        }
        __syncthreads();
    }

    // --- epilogue: gather exact fp32 prototype, proto + residual + loss ---
    float lsum = 0.f;
    for (int i = tid; i < BM * (DDIM / 4); i += THREADS) {
        int t  = i >> 6;
        int kq = i & 63;
        int id = (int)(slots[t] & 0xFFFFFFFFull);
        float4 pv = p4[(size_t)id * (DDIM / 4) + kq];
        float4 xv = x4[(size_t)(t0 + t) * (DDIM / 4) + kq];
        float4 rv = make_float4(xv.x - pv.x, xv.y - pv.y, xv.z - pv.z, xv.w - pv.w);
        size_t o = (size_t)(t0 + t) * (DDIM / 4) + kq;
        out_proto[o] = pv;
        out_res[o]   = rv;
        lsum += rv.x * rv.x + rv.y * rv.y + rv.z * rv.z + rv.w * rv.w;
    }
    sred[tid] = lsum;
    __syncthreads();
    #pragma unroll
    for (int s2 = THREADS / 2; s2 >= 1; s2 >>= 1) {
        if (tid < s2) sred[tid] += sred[tid + s2];
        __syncthreads();
    }
    if (tid == 0) g_partials[blockIdx.x] = sred[0];
}

// ===========================================================================
// Deterministic final loss reduction
// ===========================================================================
__global__ void finalize_kernel(float* __restrict__ loss_out) {
    __shared__ float s[NBLOCKS];
    int tid = threadIdx.x;
    s[tid] = g_partials[tid];
    __syncthreads();
    #pragma unroll
    for (int st = NBLOCKS / 2; st >= 1; st >>= 1) {
        if (tid < st) s[tid] += s[tid + st];
        __syncthreads();
    }
    if (tid == 0) {
        // loss = q_latent + 0.25 * e_latent = 1.25 * mean((proto - x)^2)
        *loss_out = 1.25f * s[0] / 16777216.0f;
    }
}

// ===========================================================================
extern "C" void kernel_launch(void* const* d_in, const int* in_sizes, int n_in,
                              void* d_out, int out_size) {
    const float4* x4 = (const float4*)d_in[0];
    const float4* p4 = (const float4*)d_in[1];
    float* out = (float*)d_out;

    float4* out_proto = (float4*)out;               // [65536, 256]
    float4* out_res   = (float4*)(out + 16777216);  // [65536, 256]
    float*  loss_out  = out + 33554432;             // scalar

    cudaFuncSetAttribute(vq_main_kernel,
                         cudaFuncAttributeMaxDynamicSharedMemorySize, SMEM_TOTAL);

    prep_kernel<<<64, 256>>>(p4);   // 512 warps: one per prototype
    vq_main_kernel<<<NBLOCKS, THREADS, SMEM_TOTAL>>>(x4, p4, out_proto, out_res);
    finalize_kernel<<<1, NBLOCKS>>>(loss_out);
}

// round 6
// speedup vs baseline: 2.4810x; 1.0934x over previous
#include <cuda_runtime.h>
#include <cuda_fp16.h>
#include <cstdint>
#include <cstddef>

// ===========================================================================
// Problem constants
// ===========================================================================
#define T_TOKENS 65536
#define DDIM     256
#define PROTOS   512
#define BM       128          // tokens per CTA
#define BN       128          // protos per chunk
#define NCHUNK   4
#define KS       64           // K-slice for streamed B
#define NSLICES  16           // NCHUNK * (DDIM/KS)
#define THREADS  256
#define NBLOCKS  (T_TOKENS / BM)   // 512

// Shared memory layout (bytes)
#define SLOT_OFF 0                          // 128 x u64 argmin slots
#define PN_OFF   1024                       // 512 fp32
#define SRED_OFF 3072                       // 256 fp32
#define AH_OFF   4096
#define A_STRH   264                        // halves per A row (528B: 4-bank rotate, conflict-free)
#define A_BYTES  (128 * A_STRH * 2)         // 67584
#define AL_OFF   (AH_OFF + A_BYTES)         // 71680
#define B_OFF    (AL_OFF + A_BYTES)         // 139264 (16B aligned)
#define B_STRH   72                         // halves per B row (144B: 4-bank rotate)
#define B_SPLITB (128 * B_STRH * 2)         // 18432
#define B_BUFB   (2 * B_SPLITB)             // 36864
#define SMEM_TOTAL (B_OFF + 2 * B_BUFB)     // 212992 (208KB)

__device__ __half g_Bh16[PROTOS * DDIM];
__device__ __half g_Bl16[PROTOS * DDIM];
__device__ float  g_pnorm[PROTOS];
__device__ float  g_partials[NBLOCKS];

// ===========================================================================
// Helpers
// ===========================================================================
__device__ __forceinline__ uint32_t smem_u32(const void* p) {
    uint32_t a;
    asm("{ .reg .u64 t; cvta.to.shared.u64 t, %1; cvt.u32.u64 %0, t; }" : "=r"(a) : "l"(p));
    return a;
}
__device__ __forceinline__ void cp_async16(uint32_t dst, const void* src) {
    asm volatile("cp.async.cg.shared.global [%0], [%1], 16;" :: "r"(dst), "l"(src) : "memory");
}
__device__ __forceinline__ void cp_commit() {
    asm volatile("cp.async.commit_group;" ::: "memory");
}
__device__ __forceinline__ void cp_wait1() {
    asm volatile("cp.async.wait_group 1;" ::: "memory");
}
__device__ __forceinline__ void cp_wait0() {
    asm volatile("cp.async.wait_group 0;" ::: "memory");
}
__device__ __forceinline__ void ldsm_x4(uint32_t& r0, uint32_t& r1, uint32_t& r2, uint32_t& r3,
                                        uint32_t addr) {
    asm volatile("ldmatrix.sync.aligned.m8n8.x4.shared.b16 {%0,%1,%2,%3}, [%4];"
                 : "=r"(r0), "=r"(r1), "=r"(r2), "=r"(r3) : "r"(addr));
}
// D += A(f16) * B(f16), m16n8k16, A row-major, B col-major, f32 accumulate
__device__ __forceinline__ void mma_f16(float* d, const uint32_t* a, const uint32_t* b) {
    asm volatile(
        "mma.sync.aligned.m16n8k16.row.col.f32.f16.f16.f32 "
        "{%0,%1,%2,%3}, {%4,%5,%6,%7}, {%8,%9}, {%0,%1,%2,%3};"
        : "+f"(d[0]), "+f"(d[1]), "+f"(d[2]), "+f"(d[3])
        : "r"(a[0]), "r"(a[1]), "r"(a[2]), "r"(a[3]), "r"(b[0]), "r"(b[1]));
}
// Split pair (a = even k -> low half, b = odd k -> high half) into h/l fp16 words
__device__ __forceinline__ void split_h2(float a, float b, uint32_t& hw, uint32_t& lw) {
    __half ha = __float2half_rn(a), hb = __float2half_rn(b);
    float la = a - __half2float(ha);
    float lb = b - __half2float(hb);
    __half hla = __float2half_rn(la), hlb = __float2half_rn(lb);
    hw = (uint32_t)__half_as_ushort(ha) | ((uint32_t)__half_as_ushort(hb) << 16);
    lw = (uint32_t)__half_as_ushort(hla) | ((uint32_t)__half_as_ushort(hlb) << 16);
}

// ===========================================================================
// Prep: warp-per-prototype fp16 split + shfl-reduced norms (deterministic)
// ===========================================================================
__global__ void prep_kernel(const float4* __restrict__ p4) {
    int gtid = blockIdx.x * blockDim.x + threadIdx.x;
    int r    = gtid >> 5;
    int lane = gtid & 31;
    if (r >= PROTOS) return;
    const float4* src = p4 + (size_t)r * (DDIM / 4) + lane * 2;
    float4 v0 = src[0];
    float4 v1 = src[1];
    float f[8] = {v0.x, v0.y, v0.z, v0.w, v1.x, v1.y, v1.z, v1.w};
    uint32_t hw[4], lw[4];
    float nrm = 0.f;
    #pragma unroll
    for (int j = 0; j < 4; ++j) {
        split_h2(f[2 * j], f[2 * j + 1], hw[j], lw[j]);
        nrm += f[2 * j] * f[2 * j] + f[2 * j + 1] * f[2 * j + 1];
    }
    *(uint4*)(g_Bh16 + (size_t)r * DDIM + lane * 8) = make_uint4(hw[0], hw[1], hw[2], hw[3]);
    *(uint4*)(g_Bl16 + (size_t)r * DDIM + lane * 8) = make_uint4(lw[0], lw[1], lw[2], lw[3]);
    #pragma unroll
    for (int off = 16; off >= 1; off >>= 1)
        nrm += __shfl_xor_sync(0xffffffffu, nrm, off);
    if (lane == 0) g_pnorm[r] = nrm;
}

// ===========================================================================
// Main kernel: fp16x2-split (3-term) tensor-core distance GEMM + fused VQ
// ===========================================================================
__global__ __launch_bounds__(THREADS, 1)
void vq_main_kernel(const float4* __restrict__ x4,
                    const float4* __restrict__ p4,
                    float4* __restrict__ out_proto,
                    float4* __restrict__ out_res) {
    extern __shared__ unsigned char smem[];
    const uint32_t sb = smem_u32(smem);
    unsigned long long* slots = (unsigned long long*)(smem + SLOT_OFF);
    float*  spn  = (float*)(smem + PN_OFF);
    float*  sred = (float*)(smem + SRED_OFF);
    __half* AhP  = (__half*)(smem + AH_OFF);
    __half* AlP  = (__half*)(smem + AL_OFF);

    const int tid  = threadIdx.x;
    const int lane = tid & 31;
    const int wid  = tid >> 5;
    const int q    = lane & 3;     // thread-in-group
    const int gq   = lane >> 2;    // group id (0..7)
    const int warpM = wid & 3;     // 4 warps along M (32 rows each)
    const int warpN = wid >> 2;    // 2 warps along N (64 cols each)
    const int t0 = blockIdx.x * BM;

    // ldmatrix per-lane base addresses (bytes):
    // A matrices 0..3: rowadd=(msel&1)*8, koff=(msel>>1)*8 ; msel = lane>>3
    const int a_row = warpM * 32 + (lane & 7) + ((lane >> 3) & 1) * 8;
    const int a_kof = (lane >> 4) * 8;
    const uint32_t aAddrH = sb + AH_OFF + (uint32_t)(a_row * A_STRH + a_kof) * 2;
    const uint32_t aAddrL = sb + AL_OFF + (uint32_t)(a_row * A_STRH + a_kof) * 2;
    // B matrices (per nfp, covering nf=2*nfp, 2*nfp+1):
    // n = warpN*64 + nfp*16 + (lane>>4)*8 + (lane&7); koff = ((lane>>3)&1)*8
    const int b_rowbase = warpN * 64 + (lane >> 4) * 8 + (lane & 7);
    const int b_kof = ((lane >> 3) & 1) * 8;

    // --- init: slots, pnorm cache, A tile split to fp16 h/l ---
    if (tid < BM) slots[tid] = 0xFFFFFFFFFFFFFFFFull;
    for (int i = tid; i < PROTOS; i += THREADS) spn[i] = g_pnorm[i];
    for (int i = tid; i < BM * (DDIM / 4); i += THREADS) {
        int m = i >> 6, kq = i & 63;
        float4 v = x4[(size_t)(t0 + m) * (DDIM / 4) + kq];
        uint32_t h0, l0, h1, l1;
        split_h2(v.x, v.y, h0, l0);
        split_h2(v.z, v.w, h1, l1);
        *(uint2*)(AhP + m * A_STRH + kq * 4) = make_uint2(h0, h1);
        *(uint2*)(AlP + m * A_STRH + kq * 4) = make_uint2(l0, l1);
    }

    float acc[2][8][4];
    #pragma unroll
    for (int mf = 0; mf < 2; ++mf)
        #pragma unroll
        for (int nf = 0; nf < 8; ++nf)
            #pragma unroll
            for (int d = 0; d < 4; ++d) acc[mf][nf][d] = 0.f;

    // --- prefetch slice 0 ---
    {
        #pragma unroll
        for (int it = 0; it < 8; ++it) {
            int flat = it * THREADS + tid;      // 2048 transfers of 16B
            int sp = flat >> 10, rest = flat & 1023;
            int n = rest >> 3, gi = rest & 7;
            uint32_t dst = sb + B_OFF + sp * B_SPLITB + (uint32_t)(n * B_STRH + gi * 8) * 2;
            const __half* src = (sp ? g_Bl16 : g_Bh16) + (size_t)n * DDIM + gi * 8;
            cp_async16(dst, src);
        }
        cp_commit();
    }

    #pragma unroll 1
    for (int g = 0; g < NSLICES; ++g) {
        // prefetch slice g+1 into buffer (g+1)&1
        if (g < NSLICES - 1) {
            int gn = g + 1;
            int chn = gn >> 2, sl = gn & 3, buf = gn & 1;
            #pragma unroll
            for (int it = 0; it < 8; ++it) {
                int flat = it * THREADS + tid;
                int sp = flat >> 10, rest = flat & 1023;
                int n = rest >> 3, gi = rest & 7;
                uint32_t dst = sb + B_OFF + buf * B_BUFB + sp * B_SPLITB
                             + (uint32_t)(n * B_STRH + gi * 8) * 2;
                const __half* src = (sp ? g_Bl16 : g_Bh16)
                                    + (size_t)(chn * BN + n) * DDIM + sl * KS + gi * 8;
                cp_async16(dst, src);
            }
            cp_commit();
            cp_wait1();
        } else {
            cp_wait0();
        }
        __syncthreads();

        // --- compute slice g (4 x k16, ldmatrix fragments) ---
        {
            const int buf = g & 1;
            const uint32_t bAddrH = sb + B_OFF + buf * B_BUFB
                                  + (uint32_t)(b_rowbase * B_STRH + b_kof) * 2;
            const uint32_t bAddrL = bAddrH + B_SPLITB;
            const int kA0 = (g & 3) * KS;

            #pragma unroll
            for (int kk = 0; kk < 4; ++kk) {
                const uint32_t aoff = (uint32_t)(kA0 + kk * 16) * 2;
                const uint32_t boff = (uint32_t)(kk * 16) * 2;

                uint32_t ah[2][4], al[2][4];
                #pragma unroll
                for (int mf = 0; mf < 2; ++mf) {
                    const uint32_t mo = (uint32_t)(mf * 16 * A_STRH) * 2;
                    ldsm_x4(ah[mf][0], ah[mf][1], ah[mf][2], ah[mf][3], aAddrH + mo + aoff);
                    ldsm_x4(al[mf][0], al[mf][1], al[mf][2], al[mf][3], aAddrL + mo + aoff);
                }
                uint32_t bh[8][2], bl[8][2];
                #pragma unroll
                for (int nfp = 0; nfp < 4; ++nfp) {
                    const uint32_t no = (uint32_t)(nfp * 16 * B_STRH) * 2;
                    ldsm_x4(bh[2 * nfp][0], bh[2 * nfp][1], bh[2 * nfp + 1][0], bh[2 * nfp + 1][1],
                            bAddrH + no + boff);
                    ldsm_x4(bl[2 * nfp][0], bl[2 * nfp][1], bl[2 * nfp + 1][0], bl[2 * nfp + 1][1],
                            bAddrL + no + boff);
                }
                // term hh
                #pragma unroll
                for (int mf = 0; mf < 2; ++mf)
                    #pragma unroll
                    for (int nf = 0; nf < 8; ++nf)
                        mma_f16(acc[mf][nf], ah[mf], bh[nf]);
                // term lh
                #pragma unroll
                for (int mf = 0; mf < 2; ++mf)
                    #pragma unroll
                    for (int nf = 0; nf < 8; ++nf)
                        mma_f16(acc[mf][nf], al[mf], bh[nf]);
                // term hl
                #pragma unroll
                for (int mf = 0; mf < 2; ++mf)
                    #pragma unroll
                    for (int nf = 0; nf < 8; ++nf)
                        mma_f16(acc[mf][nf], ah[mf], bl[nf]);
            }
        }

        // --- end of chunk: fold accumulators into argmin slots ---
        if ((g & 3) == 3) {
            const int chunk = g >> 2;
            #pragma unroll
            for (int mf = 0; mf < 2; ++mf) {
                #pragma unroll
                for (int h = 0; h < 2; ++h) {
                    int row = warpM * 32 + mf * 16 + h * 8 + gq;
                    float bestd = 3.4e38f;
                    int bi = 0;
                    #pragma unroll
                    for (int nf = 0; nf < 8; ++nf) {
                        #pragma unroll
                        for (int d = 0; d < 2; ++d) {
                            int n = chunk * BN + warpN * 64 + nf * 8 + 2 * q + d;
                            float dist = fmaf(-2.f, acc[mf][nf][h * 2 + d], spn[n]);
                            if (dist < bestd) { bestd = dist; bi = n; }
                        }
                    }
                    uint32_t mb = __float_as_uint(bestd);
                    mb ^= (mb & 0x80000000u) ? 0xFFFFFFFFu : 0x80000000u;  // orderable
                    unsigned long long key = ((unsigned long long)mb << 32) | (unsigned)bi;
                    atomicMin(&slots[row], key);
                }
            }
            #pragma unroll
            for (int mf = 0; mf < 2; ++mf)
                #pragma unroll
                for (int nf = 0; nf < 8; ++nf)
                    #pragma unroll
                    for (int d = 0; d < 4; ++d) acc[mf][nf][d] = 0.f;
        }
        __syncthreads();
    }

    // --- epilogue: gather exact fp32 prototype, proto + residual + loss ---
    float lsum = 0.f;
    for (int i = tid; i < BM * (DDIM / 4); i += THREADS) {
        int t  = i >> 6;
        int kq = i & 63;
        int id = (int)(slots[t] & 0xFFFFFFFFull);
        float4 pv = p4[(size_t)id * (DDIM / 4) + kq];
        float4 xv = x4[(size_t)(t0 + t) * (DDIM / 4) + kq];
        float4 rv = make_float4(xv.x - pv.x, xv.y - pv.y, xv.z - pv.z, xv.w - pv.w);
        size_t o = (size_t)(t0 + t) * (DDIM / 4) + kq;
        out_proto[o] = pv;
        out_res[o]   = rv;
        lsum += rv.x * rv.x + rv.y * rv.y + rv.z * rv.z + rv.w * rv.w;
    }
    sred[tid] = lsum;
    __syncthreads();
    #pragma unroll
    for (int s2 = THREADS / 2; s2 >= 1; s2 >>= 1) {
        if (tid < s2) sred[tid] += sred[tid + s2];
        __syncthreads();
    }
    if (tid == 0) g_partials[blockIdx.x] = sred[0];
}

// ===========================================================================
// Deterministic final loss reduction
// ===========================================================================
__global__ void finalize_kernel(float* __restrict__ loss_out) {
    __shared__ float s[NBLOCKS];
    int tid = threadIdx.x;
    s[tid] = g_partials[tid];
    __syncthreads();
    #pragma unroll
    for (int st = NBLOCKS / 2; st >= 1; st >>= 1) {
        if (tid < st) s[tid] += s[tid + st];
        __syncthreads();
    }
    if (tid == 0) {
        // loss = q_latent + 0.25 * e_latent = 1.25 * mean((proto - x)^2)
        *loss_out = 1.25f * s[0] / 16777216.0f;
    }
}

// ===========================================================================
extern "C" void kernel_launch(void* const* d_in, const int* in_sizes, int n_in,
                              void* d_out, int out_size) {
    const float4* x4 = (const float4*)d_in[0];
    const float4* p4 = (const float4*)d_in[1];
    float* out = (float*)d_out;

    float4* out_proto = (float4*)out;               // [65536, 256]
    float4* out_res   = (float4*)(out + 16777216);  // [65536, 256]
    float*  loss_out  = out + 33554432;             // scalar

    cudaFuncSetAttribute(vq_main_kernel,
                         cudaFuncAttributeMaxDynamicSharedMemorySize, SMEM_TOTAL);

    prep_kernel<<<64, 256>>>(p4);   // 512 warps: one per prototype
    vq_main_kernel<<<NBLOCKS, THREADS, SMEM_TOTAL>>>(x4, p4, out_proto, out_res);
    finalize_kernel<<<1, NBLOCKS>>>(loss_out);
}